// round 5
// baseline (speedup 1.0000x reference)
#include <cuda_runtime.h>
#include <math.h>

#define KC 64
#define DD 8
#define NC 36
#define CP 46
#define NBLOCKS 512
#define NTHREADS 128
#define BPT 2
#define BTOT 131072

typedef unsigned long long ull;

__device__ __align__(16) ull g_coeffp[KC * CP];
__constant__ __align__(16) ull c_coeff[KC * CP];   // 23.5 KB
__device__ float g_partials[NBLOCKS];
__device__ unsigned g_count = 0;

__device__ __forceinline__ float ex2f(float x) {
    float y; asm("ex2.approx.ftz.f32 %0, %1;" : "=f"(y) : "f"(x)); return y;
}
__device__ __forceinline__ float lg2f(float x) {
    float y; asm("lg2.approx.f32 %0, %1;" : "=f"(y) : "f"(x)); return y;
}
__device__ __forceinline__ ull fma2(ull a, ull b, ull c) {
    ull d; asm("fma.rn.f32x2 %0, %1, %2, %3;" : "=l"(d) : "l"(a), "l"(b), "l"(c)); return d;
}
__device__ __forceinline__ ull pack2(float lo, float hi) {
    ull v; asm("mov.b64 %0, {%1, %2};" : "=l"(v) : "f"(lo), "f"(hi)); return v;
}
__device__ __forceinline__ void unpack2(float& lo, float& hi, ull v) {
    asm("mov.b64 {%0, %1}, %2;" : "=f"(lo), "=f"(hi) : "l"(v));
}
__device__ __forceinline__ ull dup(float x) {
    unsigned u = __float_as_uint(x);
    return (ull)u | ((ull)u << 32);
}

// ---------------------------------------------------------------------------
// Prep (fp32): A = L^{-1} * sqrt(0.5/ln2), nw = -A@mu,
// c2n = sum(log2(Lii)) + 4*log2(2pi). Stored as DUPLICATED f32 pairs (b64).
// ---------------------------------------------------------------------------
__global__ void prep_kernel(const float* __restrict__ mu,
                            const float* __restrict__ Lc) {
    int k = threadIdx.x;
    if (k >= KC) return;

    float L[DD][DD];
    int m = 0;
#pragma unroll
    for (int i = 0; i < DD; i++)
#pragma unroll
        for (int j = 0; j <= i; j++)
            L[i][j] = Lc[k * NC + m++];

    float X[DD][DD];
#pragma unroll
    for (int j = 0; j < DD; j++) {
        X[j][j] = 1.0f / L[j][j];
#pragma unroll
        for (int i = j + 1; i < DD; i++) {
            float s = 0.0f;
            for (int t = j; t < i; t++) s = fmaf(L[i][t], X[t][j], s);
            X[i][j] = -s / L[i][i];
        }
    }
    float sumlg2 = 0.0f;
#pragma unroll
    for (int i = 0; i < DD; i++) sumlg2 += lg2f(L[i][i]);

    const float SCALE = 0.8493218003f;        // sqrt(0.5/ln2)
    const float C4LOG2PI = 10.6059845179f;    // 4*log2(2*pi)
    float c2n = sumlg2 + C4LOG2PI;

    ull* out = g_coeffp + k * CP;
    m = 0;
#pragma unroll
    for (int i = 0; i < DD; i++)
#pragma unroll
        for (int j = 0; j <= i; j++)
            out[m++] = dup(X[i][j] * SCALE);
#pragma unroll
    for (int i = 0; i < DD; i++) {
        float acc = 0.0f;
#pragma unroll
        for (int j = 0; j <= i; j++) acc = fmaf(X[i][j], mu[k * DD + j], acc);
        out[36 + i] = dup(-SCALE * acc);
    }
    out[44] = dup(c2n);
    out[45] = 0;
}

// ---------------------------------------------------------------------------
// Main: 2 rows/thread packed as one f32x2 lane. Coefficients come from
// __constant__ (uniform LDCU path — no shared/L1 crossbar traffic).
// Online base-2 logsumexp; final reduction folded in via last-block counter.
// ---------------------------------------------------------------------------
__global__ void __launch_bounds__(NTHREADS)
main_kernel(const float* __restrict__ pi, const float* __restrict__ target,
            float* __restrict__ out) {
    __shared__ float red[NTHREADS];
    __shared__ bool s_last;

    const int tid = threadIdx.x;
    const int b0 = blockIdx.x * (NTHREADS * BPT) + tid;

    // load 2 target rows, pack as f32x2 pairs
    ull tp[DD];
    {
        const float4* t0 = (const float4*)(target + (size_t)b0 * DD);
        const float4* t1 = (const float4*)(target + (size_t)(b0 + NTHREADS) * DD);
        float4 a0 = t0[0], a1 = t0[1], b0v = t1[0], b1v = t1[1];
        tp[0] = pack2(a0.x, b0v.x); tp[1] = pack2(a0.y, b0v.y);
        tp[2] = pack2(a0.z, b0v.z); tp[3] = pack2(a0.w, b0v.w);
        tp[4] = pack2(a1.x, b1v.x); tp[5] = pack2(a1.y, b1v.y);
        tp[6] = pack2(a1.z, b1v.z); tp[7] = pack2(a1.w, b1v.w);
    }

    float mx0 = -1e30f, mx1 = -1e30f, sm0 = 0.0f, sm1 = 0.0f;

#pragma unroll 1
    for (int kt = 0; kt < KC / 4; kt++) {
        float4 p0 = *((const float4*)(pi + (size_t)b0 * KC + kt * 4));
        float4 p1 = *((const float4*)(pi + (size_t)(b0 + NTHREADS) * KC + kt * 4));
        float pr0[4] = {p0.x, p0.y, p0.z, p0.w};
        float pr1[4] = {p1.x, p1.y, p1.z, p1.w};
#pragma unroll
        for (int kk = 0; kk < 4; kk++) {
            const ull* c = c_coeff + (kt * 4 + kk) * CP;
            ull z[DD];
            int m = 0;
#pragma unroll
            for (int i = 0; i < DD; i++) {
                ull acc = c[36 + i];
#pragma unroll
                for (int j = 0; j <= i; j++)
                    acc = fma2(c[m + j], tp[j], acc);
                m += i + 1;
                z[i] = acc;
            }
            ull macc = c[44];
#pragma unroll
            for (int i = 0; i < DD; i++) macc = fma2(z[i], z[i], macc);

            float mm0, mm1;
            unpack2(mm0, mm1, macc);

            float w0 = lg2f(pr0[kk] + 1e-10f) - mm0;
            float w1 = lg2f(pr1[kk] + 1e-10f) - mm1;
            float n0 = fmaxf(mx0, w0);
            float n1 = fmaxf(mx1, w1);
            sm0 = fmaf(sm0, ex2f(mx0 - n0), ex2f(w0 - n0));
            sm1 = fmaf(sm1, ex2f(mx1 - n1), ex2f(w1 - n1));
            mx0 = n0; mx1 = n1;
        }
    }

    float part = (mx0 + lg2f(sm0)) + (mx1 + lg2f(sm1));

    red[tid] = part;
    __syncthreads();
#pragma unroll
    for (int s = NTHREADS / 2; s > 0; s >>= 1) {
        if (tid < s) red[tid] += red[tid + s];
        __syncthreads();
    }
    if (tid == 0) {
        g_partials[blockIdx.x] = red[0];
        __threadfence();
        unsigned done = atomicAdd(&g_count, 1u);
        s_last = (done == NBLOCKS - 1);
    }
    __syncthreads();

    if (s_last) {
        float v = 0.0f;
#pragma unroll
        for (int i = 0; i < NBLOCKS / NTHREADS; i++)
            v += g_partials[tid + i * NTHREADS];
        red[tid] = v;
        __syncthreads();
#pragma unroll
        for (int s = NTHREADS / 2; s > 0; s >>= 1) {
            if (tid < s) red[tid] += red[tid + s];
            __syncthreads();
        }
        if (tid == 0) {
            out[0] = (float)(-0.6931471805599453 * (double)red[0] / (double)BTOT);
            g_count = 0;   // reset for next graph replay
        }
    }
}

extern "C" void kernel_launch(void* const* d_in, const int* in_sizes, int n_in,
                              void* d_out, int out_size) {
    const float* pi = (const float*)d_in[0];
    const float* mu = (const float*)d_in[1];
    const float* Lc = (const float*)d_in[2];
    const float* target = (const float*)d_in[3];

    prep_kernel<<<1, KC>>>(mu, Lc);

    // Resolve the REAL device address of g_coeffp (symbol name in host code is
    // only a shadow token — passing it directly to memcpy was the R4 bug).
    void* src = 0;
    cudaGetSymbolAddress(&src, g_coeffp);
    cudaMemcpyToSymbolAsync(c_coeff, src, sizeof(ull) * KC * CP, 0,
                            cudaMemcpyDeviceToDevice);

    main_kernel<<<NBLOCKS, NTHREADS>>>(pi, target, (float*)d_out);
}

// round 7
// speedup vs baseline: 2.1005x; 2.1005x over previous
#include <cuda_runtime.h>
#include <math.h>

#define KC 64
#define DD 8
#define NC 36
#define CP 46          // ull entries per k (36 A + 8 nw + 1 c2n + 1 pad), 368 B
#define NBLOCKS 256
#define NTHREADS 128
#define BTOT 131072

typedef unsigned long long ull;

__device__ __align__(16) ull g_coeffp[KC * CP];
__device__ float g_partials[NBLOCKS];
__device__ unsigned g_count = 0;

__device__ __forceinline__ float ex2f(float x) {
    float y; asm("ex2.approx.ftz.f32 %0, %1;" : "=f"(y) : "f"(x)); return y;
}
__device__ __forceinline__ float lg2f(float x) {
    float y; asm("lg2.approx.f32 %0, %1;" : "=f"(y) : "f"(x)); return y;
}
__device__ __forceinline__ ull fma2(ull a, ull b, ull c) {
    ull d; asm("fma.rn.f32x2 %0, %1, %2, %3;" : "=l"(d) : "l"(a), "l"(b), "l"(c)); return d;
}
__device__ __forceinline__ ull pack2(float lo, float hi) {
    ull v; asm("mov.b64 %0, {%1, %2};" : "=l"(v) : "f"(lo), "f"(hi)); return v;
}
__device__ __forceinline__ void unpack2(float& lo, float& hi, ull v) {
    asm("mov.b64 {%0, %1}, %2;" : "=f"(lo), "=f"(hi) : "l"(v));
}
__device__ __forceinline__ ull dup(float x) {
    unsigned u = __float_as_uint(x);
    return (ull)u | ((ull)u << 32);
}

// ---------------------------------------------------------------------------
// Prep (fp32): A = L^{-1} * sqrt(0.5/ln2), nw = -A@mu,
// c2n = sum(log2(Lii)) + 4*log2(2pi). Stored as DUPLICATED f32 pairs (b64).
// ---------------------------------------------------------------------------
__global__ void prep_kernel(const float* __restrict__ mu,
                            const float* __restrict__ Lc) {
    int k = threadIdx.x;
    if (k >= KC) return;

    float L[DD][DD];
    int m = 0;
#pragma unroll
    for (int i = 0; i < DD; i++)
#pragma unroll
        for (int j = 0; j <= i; j++)
            L[i][j] = Lc[k * NC + m++];

    float X[DD][DD];
#pragma unroll
    for (int j = 0; j < DD; j++) {
        X[j][j] = 1.0f / L[j][j];
#pragma unroll
        for (int i = j + 1; i < DD; i++) {
            float s = 0.0f;
            for (int t = j; t < i; t++) s = fmaf(L[i][t], X[t][j], s);
            X[i][j] = -s / L[i][i];
        }
    }
    float sumlg2 = 0.0f;
#pragma unroll
    for (int i = 0; i < DD; i++) sumlg2 += lg2f(L[i][i]);

    const float SCALE = 0.8493218003f;        // sqrt(0.5/ln2)
    const float C4LOG2PI = 10.6059845179f;    // 4*log2(2*pi)
    float c2n = sumlg2 + C4LOG2PI;

    ull* out = g_coeffp + k * CP;
    m = 0;
#pragma unroll
    for (int i = 0; i < DD; i++)
#pragma unroll
        for (int j = 0; j <= i; j++)
            out[m++] = dup(X[i][j] * SCALE);
#pragma unroll
    for (int i = 0; i < DD; i++) {
        float acc = 0.0f;
#pragma unroll
        for (int j = 0; j <= i; j++) acc = fmaf(X[i][j], mu[k * DD + j], acc);
        out[36 + i] = dup(-SCALE * acc);
    }
    out[44] = dup(c2n);
    out[45] = 0;
}

// coefficient pair access: compile-time idx -> LDS.128 half (CSE merges pairs)
#define CPAIR(cq, idx) (((idx) & 1) ? (cq)[(idx) >> 1].y : (cq)[(idx) >> 1].x)

// ---------------------------------------------------------------------------
// Main: 4 rows/thread as 2 f32x2 pairs. Coefficients broadcast from smem via
// LDS.128 (duplicated pairs). Online base-2 logsumexp; last-block reduction.
// ---------------------------------------------------------------------------
__global__ void __launch_bounds__(NTHREADS)
main_kernel(const float* __restrict__ pi, const float* __restrict__ target,
            float* __restrict__ out) {
    __shared__ __align__(16) ull sc[KC * CP];      // 23.5 KB
    __shared__ float red[NTHREADS];
    __shared__ bool s_last;

    {
        const float4* gsrc = (const float4*)g_coeffp;
        float4* sdst = (float4*)sc;
#pragma unroll
        for (int i = threadIdx.x; i < KC * CP / 2; i += NTHREADS)
            sdst[i] = gsrc[i];
    }
    __syncthreads();

    const int tid = threadIdx.x;
    const int b0 = blockIdx.x * (NTHREADS * 4) + tid;

    float t[4][DD];
#pragma unroll
    for (int r = 0; r < 4; r++) {
        const float4* tp4 = (const float4*)(target + (size_t)(b0 + r * NTHREADS) * DD);
        float4 v0 = tp4[0], v1 = tp4[1];
        t[r][0] = v0.x; t[r][1] = v0.y; t[r][2] = v0.z; t[r][3] = v0.w;
        t[r][4] = v1.x; t[r][5] = v1.y; t[r][6] = v1.z; t[r][7] = v1.w;
    }
    ull tp0[DD], tp1[DD];
#pragma unroll
    for (int j = 0; j < DD; j++) {
        tp0[j] = pack2(t[0][j], t[1][j]);
        tp1[j] = pack2(t[2][j], t[3][j]);
    }

    float mx[4], sm[4];
#pragma unroll
    for (int r = 0; r < 4; r++) { mx[r] = -1e30f; sm[r] = 0.0f; }

#pragma unroll 1
    for (int kt = 0; kt < KC / 4; kt++) {
        float p[4][4];
#pragma unroll
        for (int r = 0; r < 4; r++) {
            float4 pv = *((const float4*)(pi + (size_t)(b0 + r * NTHREADS) * KC + kt * 4));
            p[r][0] = pv.x; p[r][1] = pv.y; p[r][2] = pv.z; p[r][3] = pv.w;
        }
#pragma unroll
        for (int kk = 0; kk < 4; kk++) {
            const ulonglong2* cq =
                (const ulonglong2*)(sc + (kt * 4 + kk) * CP);
            ull macc0 = CPAIR(cq, 44), macc1 = macc0;
            int m = 0;
#pragma unroll
            for (int i = 0; i < DD; i++) {
                ull nw = CPAIR(cq, 36 + i);
                ull a0 = nw, a1 = nw;
#pragma unroll
                for (int j = 0; j <= i; j++) {
                    ull cc = CPAIR(cq, m + j);
                    a0 = fma2(cc, tp0[j], a0);
                    a1 = fma2(cc, tp1[j], a1);
                }
                m += i + 1;
                macc0 = fma2(a0, a0, macc0);
                macc1 = fma2(a1, a1, macc1);
            }
            float mm[4];
            unpack2(mm[0], mm[1], macc0);
            unpack2(mm[2], mm[3], macc1);
#pragma unroll
            for (int r = 0; r < 4; r++) {
                float w = lg2f(p[r][kk] + 1e-10f) - mm[r];
                float mn = fmaxf(mx[r], w);
                sm[r] = fmaf(sm[r], ex2f(mx[r] - mn), ex2f(w - mn));
                mx[r] = mn;
            }
        }
    }

    float part = 0.0f;
#pragma unroll
    for (int r = 0; r < 4; r++) part += mx[r] + lg2f(sm[r]);

    red[tid] = part;
    __syncthreads();
#pragma unroll
    for (int s = NTHREADS / 2; s > 0; s >>= 1) {
        if (tid < s) red[tid] += red[tid + s];
        __syncthreads();
    }
    if (tid == 0) {
        g_partials[blockIdx.x] = red[0];
        __threadfence();
        unsigned done = atomicAdd(&g_count, 1u);
        s_last = (done == NBLOCKS - 1);
    }
    __syncthreads();

    if (s_last) {
        float v = 0.0f;
#pragma unroll
        for (int i = 0; i < NBLOCKS / NTHREADS; i++)
            v += g_partials[tid + i * NTHREADS];
        red[tid] = v;
        __syncthreads();
#pragma unroll
        for (int s = NTHREADS / 2; s > 0; s >>= 1) {
            if (tid < s) red[tid] += red[tid + s];
            __syncthreads();
        }
        if (tid == 0) {
            out[0] = (float)(-0.6931471805599453 * (double)red[0] / (double)BTOT);
            g_count = 0;   // reset for next graph replay
        }
    }
}

extern "C" void kernel_launch(void* const* d_in, const int* in_sizes, int n_in,
                              void* d_out, int out_size) {
    const float* pi = (const float*)d_in[0];
    const float* mu = (const float*)d_in[1];
    const float* Lc = (const float*)d_in[2];
    const float* target = (const float*)d_in[3];

    prep_kernel<<<1, KC>>>(mu, Lc);
    main_kernel<<<NBLOCKS, NTHREADS>>>(pi, target, (float*)d_out);
}

// round 8
// speedup vs baseline: 2.3760x; 1.1311x over previous
#include <cuda_runtime.h>
#include <math.h>

#define KC 64
#define DD 8
#define NC 36
#define CP 46          // ull entries per k-PAIR: 36 A + 8 nw + 1 c2n + 1 pad
#define NKP (KC / 2)   // 32 k-pairs
#define NBLOCKS 256
#define NTHREADS 128
#define BTOT 131072

typedef unsigned long long ull;

__device__ __align__(16) ull g_coeffp[NKP * CP];
__device__ float g_partials[NBLOCKS];
__device__ unsigned g_count = 0;

__device__ __forceinline__ float ex2f(float x) {
    float y; asm("ex2.approx.ftz.f32 %0, %1;" : "=f"(y) : "f"(x)); return y;
}
__device__ __forceinline__ float lg2f(float x) {
    float y; asm("lg2.approx.f32 %0, %1;" : "=f"(y) : "f"(x)); return y;
}
__device__ __forceinline__ ull fma2(ull a, ull b, ull c) {
    ull d; asm("fma.rn.f32x2 %0, %1, %2, %3;" : "=l"(d) : "l"(a), "l"(b), "l"(c)); return d;
}
__device__ __forceinline__ ull pack2(float lo, float hi) {
    ull v; asm("mov.b64 %0, {%1, %2};" : "=l"(v) : "f"(lo), "f"(hi)); return v;
}
__device__ __forceinline__ void unpack2(float& lo, float& hi, ull v) {
    asm("mov.b64 {%0, %1}, %2;" : "=f"(lo), "=f"(hi) : "l"(v));
}

// ---------------------------------------------------------------------------
// Prep (fp32): per k, A = L^{-1}*sqrt(0.5/ln2), nw = -A@mu,
// c2n = sum(log2 Lii) + 4*log2(2pi). Then pack k-PAIRS: lane=(k_even,k_odd).
// ---------------------------------------------------------------------------
__global__ void prep_kernel(const float* __restrict__ mu,
                            const float* __restrict__ Lc) {
    __shared__ float sbuf[KC][CP];
    int k = threadIdx.x;
    if (k < KC) {
        float L[DD][DD];
        int m = 0;
#pragma unroll
        for (int i = 0; i < DD; i++)
#pragma unroll
            for (int j = 0; j <= i; j++)
                L[i][j] = Lc[k * NC + m++];

        float X[DD][DD];
#pragma unroll
        for (int j = 0; j < DD; j++) {
            X[j][j] = 1.0f / L[j][j];
#pragma unroll
            for (int i = j + 1; i < DD; i++) {
                float s = 0.0f;
                for (int t = j; t < i; t++) s = fmaf(L[i][t], X[t][j], s);
                X[i][j] = -s / L[i][i];
            }
        }
        float sumlg2 = 0.0f;
#pragma unroll
        for (int i = 0; i < DD; i++) sumlg2 += lg2f(L[i][i]);

        const float SCALE = 0.8493218003f;        // sqrt(0.5/ln2)
        const float C4LOG2PI = 10.6059845179f;    // 4*log2(2*pi)

        m = 0;
#pragma unroll
        for (int i = 0; i < DD; i++)
#pragma unroll
            for (int j = 0; j <= i; j++)
                sbuf[k][m++] = X[i][j] * SCALE;
#pragma unroll
        for (int i = 0; i < DD; i++) {
            float acc = 0.0f;
#pragma unroll
            for (int j = 0; j <= i; j++) acc = fmaf(X[i][j], mu[k * DD + j], acc);
            sbuf[k][36 + i] = -SCALE * acc;
        }
        sbuf[k][44] = sumlg2 + C4LOG2PI;
        sbuf[k][45] = 0.0f;
    }
    __syncthreads();
    if (k < NKP) {
#pragma unroll
        for (int m = 0; m < CP; m++)
            g_coeffp[k * CP + m] = pack2(sbuf[2 * k][m], sbuf[2 * k + 1][m]);
    }
}

// compile-time idx -> LDS.128 half (pairs merge into vec loads, CSE'd)
#define CPAIR(cq, idx) (((idx) & 1) ? (cq)[(idx) >> 1].y : (cq)[(idx) >> 1].x)

// ---------------------------------------------------------------------------
// Main: f32x2 lanes carry (k_even, k_odd); 4 scalar rows per thread.
// Coefficients non-duplicated in smem -> half the crossbar wavefronts of R7.
// Branchless 1-ex2 online logsumexp. Last-block final reduction.
// ---------------------------------------------------------------------------
__global__ void __launch_bounds__(NTHREADS)
main_kernel(const float* __restrict__ pi, const float* __restrict__ target,
            float* __restrict__ out) {
    __shared__ __align__(16) ull sc[NKP * CP];     // 11.5 KB
    __shared__ float red[NTHREADS];
    __shared__ bool s_last;

    {
        const float4* gsrc = (const float4*)g_coeffp;
        float4* sdst = (float4*)sc;
#pragma unroll
        for (int i = threadIdx.x; i < NKP * CP / 2; i += NTHREADS)
            sdst[i] = gsrc[i];
    }
    __syncthreads();

    const int tid = threadIdx.x;
    const int b0 = blockIdx.x * (NTHREADS * 4) + tid;

    // 4 target rows, each component duplicated into both f32x2 lanes
    ull tpd[4][DD];
#pragma unroll
    for (int r = 0; r < 4; r++) {
        const float4* tp4 = (const float4*)(target + (size_t)(b0 + r * NTHREADS) * DD);
        float4 v0 = tp4[0], v1 = tp4[1];
        tpd[r][0] = pack2(v0.x, v0.x); tpd[r][1] = pack2(v0.y, v0.y);
        tpd[r][2] = pack2(v0.z, v0.z); tpd[r][3] = pack2(v0.w, v0.w);
        tpd[r][4] = pack2(v1.x, v1.x); tpd[r][5] = pack2(v1.y, v1.y);
        tpd[r][6] = pack2(v1.z, v1.z); tpd[r][7] = pack2(v1.w, v1.w);
    }

    float mx[4], sm[4];
#pragma unroll
    for (int r = 0; r < 4; r++) { mx[r] = -1e30f; sm[r] = 0.0f; }

#pragma unroll 1
    for (int kt = 0; kt < KC / 4; kt++) {          // 4 k = 2 k-pairs per tile
        float p[4][4];
#pragma unroll
        for (int r = 0; r < 4; r++) {
            float4 pv = *((const float4*)(pi + (size_t)(b0 + r * NTHREADS) * KC + kt * 4));
            p[r][0] = pv.x; p[r][1] = pv.y; p[r][2] = pv.z; p[r][3] = pv.w;
        }
#pragma unroll
        for (int qq = 0; qq < 2; qq++) {
            const ulonglong2* cq = (const ulonglong2*)(sc + (kt * 2 + qq) * CP);

            ull a[4], macc[4];
            // i = 0
            {
                ull nw = CPAIR(cq, 36);
                ull c0 = CPAIR(cq, 0);
                ull c2 = CPAIR(cq, 44);
#pragma unroll
                for (int r = 0; r < 4; r++) a[r] = fma2(c0, tpd[r][0], nw);
#pragma unroll
                for (int r = 0; r < 4; r++) macc[r] = fma2(a[r], a[r], c2);
            }
            int m = 1;
#pragma unroll
            for (int i = 1; i < DD; i++) {
                ull nw = CPAIR(cq, 36 + i);
                ull cj0 = CPAIR(cq, m);
#pragma unroll
                for (int r = 0; r < 4; r++) a[r] = fma2(cj0, tpd[r][0], nw);
#pragma unroll
                for (int j = 1; j <= i; j++) {
                    ull cc = CPAIR(cq, m + j);
#pragma unroll
                    for (int r = 0; r < 4; r++) a[r] = fma2(cc, tpd[r][j], a[r]);
                }
                m += i + 1;
#pragma unroll
                for (int r = 0; r < 4; r++) macc[r] = fma2(a[r], a[r], macc[r]);
            }

#pragma unroll
            for (int r = 0; r < 4; r++) {
                float mm0, mm1;
                unpack2(mm0, mm1, macc[r]);
#pragma unroll
                for (int s = 0; s < 2; s++) {
                    float mmv = s ? mm1 : mm0;
                    float w = lg2f(p[r][qq * 2 + s] + 1e-10f) - mmv;
                    float d = w - mx[r];
                    float e = ex2f(fminf(d, -d));      // 2^(-|d|)
                    float shi = fmaf(sm[r], e, 1.0f);  // new max path
                    float slo = sm[r] + e;             // old max path
                    sm[r] = (d > 0.0f) ? shi : slo;
                    mx[r] = fmaxf(mx[r], w);
                }
            }
        }
    }

    float part = 0.0f;
#pragma unroll
    for (int r = 0; r < 4; r++) part += mx[r] + lg2f(sm[r]);

    red[tid] = part;
    __syncthreads();
#pragma unroll
    for (int s = NTHREADS / 2; s > 0; s >>= 1) {
        if (tid < s) red[tid] += red[tid + s];
        __syncthreads();
    }
    if (tid == 0) {
        g_partials[blockIdx.x] = red[0];
        __threadfence();
        unsigned done = atomicAdd(&g_count, 1u);
        s_last = (done == NBLOCKS - 1);
    }
    __syncthreads();

    if (s_last) {
        float v = 0.0f;
#pragma unroll
        for (int i = 0; i < NBLOCKS / NTHREADS; i++)
            v += g_partials[tid + i * NTHREADS];
        red[tid] = v;
        __syncthreads();
#pragma unroll
        for (int s = NTHREADS / 2; s > 0; s >>= 1) {
            if (tid < s) red[tid] += red[tid + s];
            __syncthreads();
        }
        if (tid == 0) {
            out[0] = (float)(-0.6931471805599453 * (double)red[0] / (double)BTOT);
            g_count = 0;   // reset for next graph replay
        }
    }
}

extern "C" void kernel_launch(void* const* d_in, const int* in_sizes, int n_in,
                              void* d_out, int out_size) {
    const float* pi = (const float*)d_in[0];
    const float* mu = (const float*)d_in[1];
    const float* Lc = (const float*)d_in[2];
    const float* target = (const float*)d_in[3];

    prep_kernel<<<1, KC>>>(mu, Lc);
    main_kernel<<<NBLOCKS, NTHREADS>>>(pi, target, (float*)d_out);
}

// round 9
// speedup vs baseline: 2.5428x; 1.0702x over previous
#include <cuda_runtime.h>
#include <math.h>

#define KC 64
#define DD 8
#define NC 36
#define CP 46          // ull entries per k-PAIR: 36 A + 8 nw + 1 c2n + 1 pad
#define NKP (KC / 2)   // 32 k-pairs
#define NBLOCKS 256
#define TX 128
#define TY 2
#define NTHREADS (TX * TY)
#define BTOT 131072

typedef unsigned long long ull;

__device__ __align__(16) ull g_coeffp[NKP * CP];
__device__ float g_partials[NBLOCKS];
__device__ unsigned g_count = 0;

__device__ __forceinline__ float ex2f(float x) {
    float y; asm("ex2.approx.ftz.f32 %0, %1;" : "=f"(y) : "f"(x)); return y;
}
__device__ __forceinline__ float lg2f(float x) {
    float y; asm("lg2.approx.f32 %0, %1;" : "=f"(y) : "f"(x)); return y;
}
__device__ __forceinline__ ull fma2(ull a, ull b, ull c) {
    ull d; asm("fma.rn.f32x2 %0, %1, %2, %3;" : "=l"(d) : "l"(a), "l"(b), "l"(c)); return d;
}
__device__ __forceinline__ ull pack2(float lo, float hi) {
    ull v; asm("mov.b64 %0, {%1, %2};" : "=l"(v) : "f"(lo), "f"(hi)); return v;
}
__device__ __forceinline__ void unpack2(float& lo, float& hi, ull v) {
    asm("mov.b64 {%0, %1}, %2;" : "=f"(lo), "=f"(hi) : "l"(v));
}

// ---------------------------------------------------------------------------
// Prep (fp32): per k, A = L^{-1}*sqrt(0.5/ln2), nw = -A@mu,
// c2n = sum(log2 Lii) + 4*log2(2pi). Then pack k-PAIRS: lane=(k_even,k_odd).
// ---------------------------------------------------------------------------
__global__ void prep_kernel(const float* __restrict__ mu,
                            const float* __restrict__ Lc) {
    __shared__ float sbuf[KC][CP];
    int k = threadIdx.x;
    if (k < KC) {
        float L[DD][DD];
        int m = 0;
#pragma unroll
        for (int i = 0; i < DD; i++)
#pragma unroll
            for (int j = 0; j <= i; j++)
                L[i][j] = Lc[k * NC + m++];

        float X[DD][DD];
#pragma unroll
        for (int j = 0; j < DD; j++) {
            X[j][j] = 1.0f / L[j][j];
#pragma unroll
            for (int i = j + 1; i < DD; i++) {
                float s = 0.0f;
                for (int t = j; t < i; t++) s = fmaf(L[i][t], X[t][j], s);
                X[i][j] = -s / L[i][i];
            }
        }
        float sumlg2 = 0.0f;
#pragma unroll
        for (int i = 0; i < DD; i++) sumlg2 += lg2f(L[i][i]);

        const float SCALE = 0.8493218003f;        // sqrt(0.5/ln2)
        const float C4LOG2PI = 10.6059845179f;    // 4*log2(2*pi)

        m = 0;
#pragma unroll
        for (int i = 0; i < DD; i++)
#pragma unroll
            for (int j = 0; j <= i; j++)
                sbuf[k][m++] = X[i][j] * SCALE;
#pragma unroll
        for (int i = 0; i < DD; i++) {
            float acc = 0.0f;
#pragma unroll
            for (int j = 0; j <= i; j++) acc = fmaf(X[i][j], mu[k * DD + j], acc);
            sbuf[k][36 + i] = -SCALE * acc;
        }
        sbuf[k][44] = sumlg2 + C4LOG2PI;
        sbuf[k][45] = 0.0f;
    }
    __syncthreads();
    if (k < NKP) {
#pragma unroll
        for (int m = 0; m < CP; m++)
            g_coeffp[k * CP + m] = pack2(sbuf[2 * k][m], sbuf[2 * k + 1][m]);
    }
}

// compile-time idx -> LDS.128 half (pairs merge into vec loads, CSE'd)
#define CPAIR(cq, idx) (((idx) & 1) ? (cq)[(idx) >> 1].y : (cq)[(idx) >> 1].x)

// ---------------------------------------------------------------------------
// Main: block (128,2). Each y-half processes 32 of the 64 components for the
// SAME 4 rows; halves merge partial logsumexp states via smem. f32x2 lanes
// carry (k_even,k_odd); coefficients non-duplicated in smem.
// ---------------------------------------------------------------------------
__global__ void __launch_bounds__(NTHREADS)
main_kernel(const float* __restrict__ pi, const float* __restrict__ target,
            float* __restrict__ out) {
    __shared__ __align__(16) ull sc[NKP * CP];     // 11.5 KB
    __shared__ float s_mx[TX][4], s_sm[TX][4];     // 4 KB merge buffers
    __shared__ float red[NTHREADS];
    __shared__ bool s_last;

    const int tid = threadIdx.x;
    const int half = threadIdx.y;
    const int flat = half * TX + tid;

    {
        const float4* gsrc = (const float4*)g_coeffp;
        float4* sdst = (float4*)sc;
#pragma unroll
        for (int i = flat; i < NKP * CP / 2; i += NTHREADS)
            sdst[i] = gsrc[i];
    }
    __syncthreads();

    const int b0 = blockIdx.x * (TX * 4) + tid;

    // 4 target rows, each component duplicated into both f32x2 lanes
    ull tpd[4][DD];
#pragma unroll
    for (int r = 0; r < 4; r++) {
        const float4* tp4 = (const float4*)(target + (size_t)(b0 + r * TX) * DD);
        float4 v0 = tp4[0], v1 = tp4[1];
        tpd[r][0] = pack2(v0.x, v0.x); tpd[r][1] = pack2(v0.y, v0.y);
        tpd[r][2] = pack2(v0.z, v0.z); tpd[r][3] = pack2(v0.w, v0.w);
        tpd[r][4] = pack2(v1.x, v1.x); tpd[r][5] = pack2(v1.y, v1.y);
        tpd[r][6] = pack2(v1.z, v1.z); tpd[r][7] = pack2(v1.w, v1.w);
    }

    float mx[4], sm[4];
#pragma unroll
    for (int r = 0; r < 4; r++) { mx[r] = -1e30f; sm[r] = 0.0f; }

    // this half's k range: tiles of 4 k (= 2 k-pairs); 8 tiles per half
#pragma unroll 1
    for (int kt = half * (KC / 8); kt < (half + 1) * (KC / 8); kt++) {
        float p[4][4];
#pragma unroll
        for (int r = 0; r < 4; r++) {
            float4 pv = *((const float4*)(pi + (size_t)(b0 + r * TX) * KC + kt * 4));
            p[r][0] = pv.x; p[r][1] = pv.y; p[r][2] = pv.z; p[r][3] = pv.w;
        }
#pragma unroll
        for (int qq = 0; qq < 2; qq++) {
            const ulonglong2* cq = (const ulonglong2*)(sc + (kt * 2 + qq) * CP);

            ull a[4], macc[4];
            {
                ull nw = CPAIR(cq, 36);
                ull c0 = CPAIR(cq, 0);
                ull c2 = CPAIR(cq, 44);
#pragma unroll
                for (int r = 0; r < 4; r++) a[r] = fma2(c0, tpd[r][0], nw);
#pragma unroll
                for (int r = 0; r < 4; r++) macc[r] = fma2(a[r], a[r], c2);
            }
            int m = 1;
#pragma unroll
            for (int i = 1; i < DD; i++) {
                ull nw = CPAIR(cq, 36 + i);
                ull cj0 = CPAIR(cq, m);
#pragma unroll
                for (int r = 0; r < 4; r++) a[r] = fma2(cj0, tpd[r][0], nw);
#pragma unroll
                for (int j = 1; j <= i; j++) {
                    ull cc = CPAIR(cq, m + j);
#pragma unroll
                    for (int r = 0; r < 4; r++) a[r] = fma2(cc, tpd[r][j], a[r]);
                }
                m += i + 1;
#pragma unroll
                for (int r = 0; r < 4; r++) macc[r] = fma2(a[r], a[r], macc[r]);
            }

#pragma unroll
            for (int r = 0; r < 4; r++) {
                float mm0, mm1;
                unpack2(mm0, mm1, macc[r]);
#pragma unroll
                for (int s = 0; s < 2; s++) {
                    float mmv = s ? mm1 : mm0;
                    float w = lg2f(p[r][qq * 2 + s] + 1e-10f) - mmv;
                    float d = w - mx[r];
                    float e = ex2f(fminf(d, -d));      // 2^(-|d|)
                    float shi = fmaf(sm[r], e, 1.0f);  // new max path
                    float slo = sm[r] + e;             // old max path
                    sm[r] = (d > 0.0f) ? shi : slo;
                    mx[r] = fmaxf(mx[r], w);
                }
            }
        }
    }

    // merge halves: y=1 publishes, y=0 combines
    if (half == 1) {
#pragma unroll
        for (int r = 0; r < 4; r++) { s_mx[tid][r] = mx[r]; s_sm[tid][r] = sm[r]; }
    }
    __syncthreads();

    float part = 0.0f;
    if (half == 0) {
#pragma unroll
        for (int r = 0; r < 4; r++) {
            float mx1 = s_mx[tid][r], sm1 = s_sm[tid][r];
            float mn = fmaxf(mx[r], mx1);
            float s = fmaf(sm[r], ex2f(mx[r] - mn), sm1 * ex2f(mx1 - mn));
            part += mn + lg2f(s);
        }
    }

    red[flat] = part;
    __syncthreads();
#pragma unroll
    for (int s = NTHREADS / 2; s > 0; s >>= 1) {
        if (flat < s) red[flat] += red[flat + s];
        __syncthreads();
    }
    if (flat == 0) {
        g_partials[blockIdx.x] = red[0];
        __threadfence();
        unsigned done = atomicAdd(&g_count, 1u);
        s_last = (done == NBLOCKS - 1);
    }
    __syncthreads();

    if (s_last) {
        float v = (flat < NBLOCKS) ? g_partials[flat] : 0.0f;
        red[flat] = v;
        __syncthreads();
#pragma unroll
        for (int s = NTHREADS / 2; s > 0; s >>= 1) {
            if (flat < s) red[flat] += red[flat + s];
            __syncthreads();
        }
        if (flat == 0) {
            out[0] = (float)(-0.6931471805599453 * (double)red[0] / (double)BTOT);
            g_count = 0;   // reset for next graph replay
        }
    }
}

extern "C" void kernel_launch(void* const* d_in, const int* in_sizes, int n_in,
                              void* d_out, int out_size) {
    const float* pi = (const float*)d_in[0];
    const float* mu = (const float*)d_in[1];
    const float* Lc = (const float*)d_in[2];
    const float* target = (const float*)d_in[3];

    prep_kernel<<<1, KC>>>(mu, Lc);
    dim3 blk(TX, TY);
    main_kernel<<<NBLOCKS, blk>>>(pi, target, (float*)d_out);
}